// round 5
// baseline (speedup 1.0000x reference)
#include <cuda_runtime.h>
#include <cuda_bf16.h>
#include <cstdint>

// Problem constants
#define B_     64
#define H_     512
#define W_     512
#define C_     3
#define G_     64
#define K_     3
#define D_IN   (K_*G_*G_*C_)   // 36864
#define HG_    128
#define HL_    128

// GEMM split-K config
#define NCHUNK 288
#define DC     128             // K-dims per CTA chunk (NCHUNK*DC == D_IN)

// Scratch (device globals; no runtime allocation allowed)
__device__ float g_phi[(size_t)B_ * D_IN];            // 9.4 MB
__device__ float g_part[(size_t)NCHUNK * B_ * HG_];   // 9.4 MB

__device__ __forceinline__ uint32_t smem_u32(const void* p) {
    uint32_t a;
    asm("{ .reg .u64 t; cvta.to.shared.u64 t, %1; cvt.u32.u64 %0, t; }"
        : "=r"(a) : "l"(p));
    return a;
}

// ---------------------------------------------------------------------------
// Kernel 1: glimpse extraction + avg pooling (unchanged from R2: 15.5us)
// ---------------------------------------------------------------------------
template<int KK>
__device__ __forceinline__ void extract_impl(
    const float* __restrict__ x, const float* __restrict__ l,
    float* __restrict__ buf, int gy0, int b, int tid)
{
    constexpr int f      = 1 << KK;
    constexpr int r      = 4 >> KK;
    constexpr int size   = G_ * f;
    constexpr int rowlen = size * 3;

    const float lx = __ldg(&l[b * 2 + 0]);
    const float ly = __ldg(&l[b * 2 + 1]);
    const int cx = (int)((0.5f * (lx + 1.0f)) * 512.0f);
    const int cy = (int)((0.5f * (ly + 1.0f)) * 512.0f);
    const int xs = cx - size / 2;
    const int ys = cy - size / 2 + gy0 * f;

    const int jlo = (xs < 0 ? -xs : 0) * 3;
    const int xe  = xs + size;
    const int jhi = ((xe > W_ ? W_ : xe) - xs) * 3;

    #pragma unroll
    for (int rr = 0; rr < 4; rr++) {
        const int y = ys + rr;
        const bool yok = (y >= 0) && (y < H_);
        const float* rowp = x + (((size_t)b * H_ + y) * W_ + xs) * C_;
        #pragma unroll
        for (int it = 0; it < (rowlen + 191) / 192; it++) {
            const int j = tid + it * 192;
            float v = 0.0f;
            if (yok && j >= jlo && j < jhi) v = __ldg(rowp + j);
            buf[rr * rowlen + j] = v;
        }
    }
    __syncthreads();

    const int gx = tid / 3;
    const int c  = tid - gx * 3;
    constexpr float inv = 1.0f / (float)(f * f);

    #pragma unroll
    for (int orow = 0; orow < r; orow++) {
        float s = 0.0f;
        #pragma unroll
        for (int dy = 0; dy < f; dy++)
            #pragma unroll
            for (int dx = 0; dx < f; dx++)
                s += buf[(orow * f + dy) * rowlen + (gx * f + dx) * 3 + c];
        g_phi[(size_t)b * D_IN + (KK * G_ + gy0 + orow) * (G_ * C_) + tid] = s * inv;
    }
}

__global__ __launch_bounds__(192) void extract_kernel(
    const float* __restrict__ x, const float* __restrict__ l)
{
    __shared__ float buf[4 * 768];
    const int bx  = blockIdx.x;
    const int b   = blockIdx.y;
    const int tid = threadIdx.x;

    if (bx < 16)       extract_impl<0>(x, l, buf, bx * 4, b, tid);
    else if (bx < 48)  extract_impl<1>(x, l, buf, (bx - 16) * 2, b, tid);
    else               extract_impl<2>(x, l, buf, bx - 48, b, tid);
}

// ---------------------------------------------------------------------------
// Kernel 2: split-K GEMM via mma.sync bf16 (portable HMMA), bf16x3 split for
// fp32-grade accuracy: D = Ah*Bh + Ah*Bl + Al*Bh, fp32 accumulate.
// Grid NCHUNK=288, 256 threads (8 warps = 4 m-tiles x 2 n-halves).
// A: phi slice 64x128; B: W1 slice transposed to [n][k] 128x128.
// ---------------------------------------------------------------------------
#define KSTR   136                       // padded K stride in bf16 (272B rows)
#define A_TILE (64 * KSTR * 2)           // 17408 B
#define B_TILE (128 * KSTR * 2)          // 34816 B
#define OFF_AH 0
#define OFF_AL A_TILE
#define OFF_BH (2 * A_TILE)
#define OFF_BL (2 * A_TILE + B_TILE)
#define SMEM_GEMM (2 * A_TILE + 2 * B_TILE)   // 104448 B

__device__ __forceinline__ void ldsm_x4(uint32_t a[4], uint32_t addr) {
    asm volatile("ldmatrix.sync.aligned.m8n8.x4.shared.b16 {%0,%1,%2,%3}, [%4];"
                 : "=r"(a[0]), "=r"(a[1]), "=r"(a[2]), "=r"(a[3]) : "r"(addr));
}
__device__ __forceinline__ void ldsm_x2(uint32_t b[2], uint32_t addr) {
    asm volatile("ldmatrix.sync.aligned.m8n8.x2.shared.b16 {%0,%1}, [%2];"
                 : "=r"(b[0]), "=r"(b[1]) : "r"(addr));
}
__device__ __forceinline__ void mma_bf16(
    float c[4], const uint32_t a[4], const uint32_t b[2])
{
    asm volatile(
        "mma.sync.aligned.m16n8k16.row.col.f32.bf16.bf16.f32 "
        "{%0,%1,%2,%3}, {%4,%5,%6,%7}, {%8,%9}, {%0,%1,%2,%3};"
        : "+f"(c[0]), "+f"(c[1]), "+f"(c[2]), "+f"(c[3])
        : "r"(a[0]), "r"(a[1]), "r"(a[2]), "r"(a[3]), "r"(b[0]), "r"(b[1]));
}

__device__ __forceinline__ uint32_t hi_lo_pack(float v0, float v1, uint32_t& lo_out)
{
    __nv_bfloat16 h0 = __float2bfloat16(v0);
    __nv_bfloat16 h1 = __float2bfloat16(v1);
    __nv_bfloat16 e0 = __float2bfloat16(v0 - __bfloat162float(h0));
    __nv_bfloat16 e1 = __float2bfloat16(v1 - __bfloat162float(h1));
    __nv_bfloat162 hp; hp.x = h0; hp.y = h1;
    __nv_bfloat162 lp; lp.x = e0; lp.y = e1;
    lo_out = *reinterpret_cast<uint32_t*>(&lp);
    return *reinterpret_cast<uint32_t*>(&hp);
}

__global__ __launch_bounds__(256) void gemm_mma_kernel(const float* __restrict__ W1)
{
    extern __shared__ char smem[];
    const uint32_t sb = smem_u32(smem);
    const int tid  = threadIdx.x;
    const int wid  = tid >> 5;
    const int lane = tid & 31;
    const int d0   = blockIdx.x * DC;

    // ---- fill A (phi 64 x 128) hi/lo, rows m, padded stride KSTR ----
    for (int idx = tid; idx < 64 * 64; idx += 256) {
        const int m  = idx >> 6;
        const int kp = idx & 63;                     // k pair: k = 2*kp
        const float2 p = *reinterpret_cast<const float2*>(
            &g_phi[(size_t)m * D_IN + d0 + 2 * kp]);
        uint32_t lo, hi = hi_lo_pack(p.x, p.y, lo);
        const int off = m * (KSTR * 2) + kp * 4;     // bytes
        *reinterpret_cast<uint32_t*>(smem + OFF_AH + off) = hi;
        *reinterpret_cast<uint32_t*>(smem + OFF_AL + off) = lo;
    }

    // ---- fill B^T (128 n-rows x 128 k) hi/lo: B[n][k] = W1[d0+k][n] ----
    for (int idx = tid; idx < 64 * 128; idx += 256) {
        const int kk = idx >> 7;                     // k pair
        const int n  = idx & 127;                    // coalesced over W1 rows
        const float v0 = __ldg(&W1[(size_t)(d0 + 2 * kk)     * HG_ + n]);
        const float v1 = __ldg(&W1[(size_t)(d0 + 2 * kk + 1) * HG_ + n]);
        uint32_t lo, hi = hi_lo_pack(v0, v1, lo);
        const int off = n * (KSTR * 2) + kk * 4;
        *reinterpret_cast<uint32_t*>(smem + OFF_BH + off) = hi;
        *reinterpret_cast<uint32_t*>(smem + OFF_BL + off) = lo;
    }
    __syncthreads();

    // ---- warp tiling: mt = wid>>1 (m16), nh = wid&1 (n64 = 8 n-tiles) ----
    const int mt = wid >> 1;
    const int nh = wid & 1;

    // ldmatrix address offsets (bytes, relative to tile base)
    const uint32_t aRel = (uint32_t)((mt * 16 + (lane & 15)) * (KSTR * 2)
                                     + (lane >> 4) * 16);
    const uint32_t bRel = (uint32_t)((nh * 64 + (lane & 7)) * (KSTR * 2)
                                     + ((lane >> 3) & 3 & 1) * 16
                                     + ((lane >> 3) & 1) * 0);  // see below
    // lanes 0-15 feed x2; give lanes 16-31 harmless duplicates:
    const uint32_t bRelFix = (uint32_t)((nh * 64 + (lane & 7)) * (KSTR * 2)
                                        + ((lane >> 3) & 1) * 16);

    float acc[8][4];
    #pragma unroll
    for (int nt = 0; nt < 8; nt++)
        #pragma unroll
        for (int j = 0; j < 4; j++) acc[nt][j] = 0.0f;

    #pragma unroll
    for (int pass = 0; pass < 3; pass++) {
        const uint32_t aBase = sb + ((pass == 2) ? OFF_AL : OFF_AH) + aRel;
        const uint32_t bBase = sb + ((pass == 1) ? OFF_BL : OFF_BH) + bRelFix;
        #pragma unroll
        for (int kt = 0; kt < 8; kt++) {
            uint32_t a[4];
            ldsm_x4(a, aBase + kt * 32);
            #pragma unroll
            for (int nt = 0; nt < 8; nt++) {
                uint32_t b[2];
                ldsm_x2(b, bBase + nt * 8 * (KSTR * 2) + kt * 32);
                mma_bf16(acc[nt], a, b);
            }
        }
    }

    // ---- epilogue: write 64x128 partial tile ----
    float* part = &g_part[(size_t)blockIdx.x * (B_ * HG_)];
    const int qid = lane >> 2;        // 0..7
    const int tq  = lane & 3;         // 0..3
    const int row0 = mt * 16 + qid;
    #pragma unroll
    for (int nt = 0; nt < 8; nt++) {
        const int col = nh * 64 + nt * 8 + tq * 2;
        float2 v0; v0.x = acc[nt][0]; v0.y = acc[nt][1];
        float2 v1; v1.x = acc[nt][2]; v1.y = acc[nt][3];
        *reinterpret_cast<float2*>(part + row0 * HG_ + col) = v0;
        *reinterpret_cast<float2*>(part + (row0 + 8) * HG_ + col) = v1;
    }
}

// ---------------------------------------------------------------------------
// Kernel 3: reduce partials + bias + relu + l-branch (unchanged)
// ---------------------------------------------------------------------------
__global__ __launch_bounds__(512) void finalize_kernel(
    const float* __restrict__ l, const float* __restrict__ b1,
    const float* __restrict__ W2, const float* __restrict__ b2,
    float* __restrict__ out)
{
    __shared__ float red[4][HG_];
    const int b = blockIdx.x;
    const int tid = threadIdx.x;
    const int h = tid & 127;
    const int p = tid >> 7;

    float s = 0.0f;
    #pragma unroll 8
    for (int c = p; c < NCHUNK; c += 4)
        s += g_part[(size_t)c * (B_ * HG_) + b * HG_ + h];
    red[p][h] = s;
    __syncthreads();

    if (p == 0) {
        const float v = red[0][h] + red[1][h] + red[2][h] + red[3][h] + b1[h];
        out[b * (HG_ + HL_) + h] = fmaxf(v, 0.0f);
        const float lw = l[b * 2 + 0] * W2[h] + l[b * 2 + 1] * W2[HL_ + h] + b2[h];
        out[b * (HG_ + HL_) + HG_ + h] = fmaxf(lw, 0.0f);
    }
}

// ---------------------------------------------------------------------------
extern "C" void kernel_launch(void* const* d_in, const int* in_sizes, int n_in,
                              void* d_out, int out_size)
{
    const float* x  = (const float*)d_in[0];
    const float* l  = (const float*)d_in[1];
    const float* W1 = (const float*)d_in[2];
    const float* b1 = (const float*)d_in[3];
    const float* W2 = (const float*)d_in[4];
    const float* b2 = (const float*)d_in[5];
    float* out = (float*)d_out;

    static bool attr_set = false;
    if (!attr_set) {
        cudaFuncSetAttribute(gemm_mma_kernel,
                             cudaFuncAttributeMaxDynamicSharedMemorySize, SMEM_GEMM);
        attr_set = true;
    }

    dim3 eg(112, B_);
    extract_kernel<<<eg, 192>>>(x, l);
    gemm_mma_kernel<<<NCHUNK, 256, SMEM_GEMM>>>(W1);
    finalize_kernel<<<B_, 512>>>(l, b1, W2, b2, out);
}

// round 6
// speedup vs baseline: 1.2992x; 1.2992x over previous
#include <cuda_runtime.h>
#include <cuda_bf16.h>
#include <cstdint>

// Problem constants
#define B_     64
#define H_     512
#define W_     512
#define C_     3
#define G_     64
#define K_     3
#define D_IN   (K_*G_*G_*C_)   // 36864
#define HG_    128
#define HL_    128

// GEMM split-K config
#define NCHUNK 144
#define DC     256             // K-dims per CTA chunk (NCHUNK*DC == D_IN)

// Scratch (device globals; no runtime allocation allowed)
__device__ float g_phi[(size_t)B_ * D_IN];            // 9.4 MB
__device__ float g_part[(size_t)NCHUNK * B_ * HG_];   // 4.7 MB

__device__ __forceinline__ uint32_t smem_u32(const void* p) {
    uint32_t a;
    asm("{ .reg .u64 t; cvta.to.shared.u64 t, %1; cvt.u32.u64 %0, t; }"
        : "=r"(a) : "l"(p));
    return a;
}

// ---------------------------------------------------------------------------
// Kernel 1: fused multi-scale glimpse extraction + avg pooling (v3)
//
// One CTA per (gy2 in [0,64), b). Stages the 4 source rows of the k=2 window
// (256 px * 3 ch = 768 floats each) ONCE, then derives:
//   - k=2 output row gy2               (4x4 average pool)
//   - k=1 rows 2*gy2-32+{0,1}          (2x2 pool, central 128 cols) gy2 in [16,48)
//   - k=0 rows 4*gy2-96+{0..3}         (direct copy, central 64 cols) gy2 in [24,40)
// x is read exactly once per needed byte: 50 MB total.
// ---------------------------------------------------------------------------
__global__ __launch_bounds__(192) void extract_kernel(
    const float* __restrict__ x, const float* __restrict__ l)
{
    __shared__ float buf[4 * 768];

    const int gy2 = blockIdx.x;
    const int b   = blockIdx.y;
    const int tid = threadIdx.x;

    // denormalize coords exactly like reference: trunc((0.5*(l+1))*512)
    const float lx = __ldg(&l[b * 2 + 0]);
    const float ly = __ldg(&l[b * 2 + 1]);
    const int cx = (int)((0.5f * (lx + 1.0f)) * 512.0f);
    const int cy = (int)((0.5f * (ly + 1.0f)) * 512.0f);
    const int xs = cx - 128;
    const int ys = cy - 128 + gy2 * 4;

    const int jlo = (xs < 0 ? -xs : 0) * 3;
    const int xe  = xs + 256;
    const int jhi = ((xe > W_ ? W_ : xe) - xs) * 3;

    // stage 4 contiguous source rows (zero-filled OOB)
    #pragma unroll
    for (int rr = 0; rr < 4; rr++) {
        const int y = ys + rr;
        const bool yok = (y >= 0) && (y < H_);
        const float* rowp = x + (((size_t)b * H_ + y) * W_ + xs) * C_;
        #pragma unroll
        for (int it = 0; it < 4; it++) {
            const int j = tid + it * 192;
            float v = 0.0f;
            if (yok && j >= jlo && j < jhi) v = __ldg(rowp + j);
            buf[rr * 768 + j] = v;
        }
    }
    __syncthreads();

    const int gx = tid / 3;
    const int c  = tid - gx * 3;
    float* phiB = &g_phi[(size_t)b * D_IN];

    // ---- k=2: pool 4x4 ----
    {
        float s = 0.0f;
        #pragma unroll
        for (int dy = 0; dy < 4; dy++)
            #pragma unroll
            for (int dx = 0; dx < 4; dx++)
                s += buf[dy * 768 + (gx * 4 + dx) * 3 + c];
        phiB[(2 * G_ + gy2) * (G_ * C_) + tid] = s * (1.0f / 16.0f);
    }

    // ---- k=1: two output rows, pool 2x2 over central 128 cols ----
    if (gy2 >= 16 && gy2 < 48) {
        #pragma unroll
        for (int h = 0; h < 2; h++) {
            const int gy1 = 2 * gy2 - 32 + h;
            float s = 0.0f;
            #pragma unroll
            for (int dy = 0; dy < 2; dy++)
                #pragma unroll
                for (int dx = 0; dx < 2; dx++)
                    s += buf[(2 * h + dy) * 768 + (64 + gx * 2 + dx) * 3 + c];
            phiB[(G_ + gy1) * (G_ * C_) + tid] = s * 0.25f;
        }
    }

    // ---- k=0: four output rows, direct copy of central 64 cols ----
    if (gy2 >= 24 && gy2 < 40) {
        #pragma unroll
        for (int rr = 0; rr < 4; rr++) {
            const int gy0 = 4 * gy2 - 96 + rr;
            phiB[gy0 * (G_ * C_) + tid] = buf[rr * 768 + (96 + gx) * 3 + c];
        }
    }
}

// ---------------------------------------------------------------------------
// Kernel 2: split-K GEMM via mma.sync bf16 (HMMA), bf16x3 compensated split:
// D = Ah*Bh + Ah*Bl + Al*Bh, fp32 accumulate. Grid 144, 256 threads.
// Each CTA owns DC=256 K-dims, processed as 2 slabs of 128 through smem;
// accumulators persist in registers across slabs; partials written once.
// ---------------------------------------------------------------------------
#define KSTR   136                       // padded K stride in bf16 (272B rows)
#define A_TILE (64 * KSTR * 2)           // 17408 B
#define B_TILE (128 * KSTR * 2)          // 34816 B
#define OFF_AH 0
#define OFF_AL A_TILE
#define OFF_BH (2 * A_TILE)
#define OFF_BL (2 * A_TILE + B_TILE)
#define SMEM_GEMM (2 * A_TILE + 2 * B_TILE)   // 104448 B

__device__ __forceinline__ void ldsm_x4(uint32_t a[4], uint32_t addr) {
    asm volatile("ldmatrix.sync.aligned.m8n8.x4.shared.b16 {%0,%1,%2,%3}, [%4];"
                 : "=r"(a[0]), "=r"(a[1]), "=r"(a[2]), "=r"(a[3]) : "r"(addr));
}
__device__ __forceinline__ void mma_bf16(
    float c[4], const uint32_t a[4], uint32_t b0, uint32_t b1)
{
    asm volatile(
        "mma.sync.aligned.m16n8k16.row.col.f32.bf16.bf16.f32 "
        "{%0,%1,%2,%3}, {%4,%5,%6,%7}, {%8,%9}, {%0,%1,%2,%3};"
        : "+f"(c[0]), "+f"(c[1]), "+f"(c[2]), "+f"(c[3])
        : "r"(a[0]), "r"(a[1]), "r"(a[2]), "r"(a[3]), "r"(b0), "r"(b1));
}

__device__ __forceinline__ uint32_t hi_lo_pack(float v0, float v1, uint32_t& lo_out)
{
    __nv_bfloat16 h0 = __float2bfloat16(v0);
    __nv_bfloat16 h1 = __float2bfloat16(v1);
    __nv_bfloat16 e0 = __float2bfloat16(v0 - __bfloat162float(h0));
    __nv_bfloat16 e1 = __float2bfloat16(v1 - __bfloat162float(h1));
    __nv_bfloat162 hp; hp.x = h0; hp.y = h1;
    __nv_bfloat162 lp; lp.x = e0; lp.y = e1;
    lo_out = *reinterpret_cast<uint32_t*>(&lp);
    return *reinterpret_cast<uint32_t*>(&hp);
}

__global__ __launch_bounds__(256) void gemm_mma_kernel(const float* __restrict__ W1)
{
    extern __shared__ char smem[];
    const uint32_t sb = smem_u32(smem);
    const int tid  = threadIdx.x;
    const int wid  = tid >> 5;
    const int lane = tid & 31;

    // warp tiling: mt = wid>>1 (m16), nh = wid&1 (n64 = 8 n-tiles)
    const int mt = wid >> 1;
    const int nh = wid & 1;

    // ldmatrix relative offsets (bytes)
    const uint32_t aRel = (uint32_t)((mt * 16 + (lane & 15)) * (KSTR * 2)
                                     + (lane >> 4) * 16);
    // B x4: groups g=lane>>3: n offset = (g>>1)*8, k offset = (g&1)*16
    const uint32_t bRel = (uint32_t)((nh * 64 + ((lane >> 4) * 8) + (lane & 7)) * (KSTR * 2)
                                     + (((lane >> 3) & 1) * 16));

    float acc[8][4];
    #pragma unroll
    for (int nt = 0; nt < 8; nt++)
        #pragma unroll
        for (int j = 0; j < 4; j++) acc[nt][j] = 0.0f;

    for (int slab = 0; slab < 2; slab++) {
        const int d0 = blockIdx.x * DC + slab * 128;

        if (slab) __syncthreads();   // protect smem reuse

        // ---- fill A (phi 64 x 128) hi/lo ----
        for (int idx = tid; idx < 64 * 64; idx += 256) {
            const int m  = idx >> 6;
            const int kp = idx & 63;
            const float2 p = *reinterpret_cast<const float2*>(
                &g_phi[(size_t)m * D_IN + d0 + 2 * kp]);
            uint32_t lo, hi = hi_lo_pack(p.x, p.y, lo);
            const int off = m * (KSTR * 2) + kp * 4;
            *reinterpret_cast<uint32_t*>(smem + OFF_AH + off) = hi;
            *reinterpret_cast<uint32_t*>(smem + OFF_AL + off) = lo;
        }

        // ---- fill B^T (128 n x 128 k): B[n][k] = W1[d0+k][n] ----
        for (int idx = tid; idx < 64 * 128; idx += 256) {
            const int kk = idx >> 7;
            const int n  = idx & 127;
            const float v0 = __ldg(&W1[(size_t)(d0 + 2 * kk)     * HG_ + n]);
            const float v1 = __ldg(&W1[(size_t)(d0 + 2 * kk + 1) * HG_ + n]);
            uint32_t lo, hi = hi_lo_pack(v0, v1, lo);
            const int off = n * (KSTR * 2) + kk * 4;
            *reinterpret_cast<uint32_t*>(smem + OFF_BH + off) = hi;
            *reinterpret_cast<uint32_t*>(smem + OFF_BL + off) = lo;
        }
        __syncthreads();

        // ---- 3 compensated passes over this slab ----
        #pragma unroll
        for (int pass = 0; pass < 3; pass++) {
            const uint32_t aBase = sb + ((pass == 2) ? OFF_AL : OFF_AH) + aRel;
            const uint32_t bBase = sb + ((pass == 1) ? OFF_BL : OFF_BH) + bRel;
            #pragma unroll
            for (int kt = 0; kt < 8; kt++) {
                uint32_t a[4];
                ldsm_x4(a, aBase + kt * 32);
                #pragma unroll
                for (int np = 0; np < 4; np++) {      // pairs of n-tiles
                    uint32_t bq[4];
                    ldsm_x4(bq, bBase + np * 16 * (KSTR * 2) + kt * 32);
                    mma_bf16(acc[np * 2 + 0], a, bq[0], bq[1]);
                    mma_bf16(acc[np * 2 + 1], a, bq[2], bq[3]);
                }
            }
        }
    }

    // ---- epilogue: write 64x128 partial tile ----
    float* part = &g_part[(size_t)blockIdx.x * (B_ * HG_)];
    const int qid = lane >> 2;
    const int tq  = lane & 3;
    const int row0 = mt * 16 + qid;
    #pragma unroll
    for (int nt = 0; nt < 8; nt++) {
        const int col = nh * 64 + nt * 8 + tq * 2;
        float2 v0; v0.x = acc[nt][0]; v0.y = acc[nt][1];
        float2 v1; v1.x = acc[nt][2]; v1.y = acc[nt][3];
        *reinterpret_cast<float2*>(part + row0 * HG_ + col) = v0;
        *reinterpret_cast<float2*>(part + (row0 + 8) * HG_ + col) = v1;
    }
}

// ---------------------------------------------------------------------------
// Kernel 3: reduce partials + bias + relu + l-branch.
// ---------------------------------------------------------------------------
__global__ __launch_bounds__(512) void finalize_kernel(
    const float* __restrict__ l, const float* __restrict__ b1,
    const float* __restrict__ W2, const float* __restrict__ b2,
    float* __restrict__ out)
{
    __shared__ float red[4][HG_];
    const int b = blockIdx.x;
    const int tid = threadIdx.x;
    const int h = tid & 127;
    const int p = tid >> 7;

    float s = 0.0f;
    #pragma unroll 9
    for (int c = p; c < NCHUNK; c += 4)
        s += g_part[(size_t)c * (B_ * HG_) + b * HG_ + h];
    red[p][h] = s;
    __syncthreads();

    if (p == 0) {
        const float v = red[0][h] + red[1][h] + red[2][h] + red[3][h] + b1[h];
        out[b * (HG_ + HL_) + h] = fmaxf(v, 0.0f);
        const float lw = l[b * 2 + 0] * W2[h] + l[b * 2 + 1] * W2[HL_ + h] + b2[h];
        out[b * (HG_ + HL_) + HG_ + h] = fmaxf(lw, 0.0f);
    }
}

// ---------------------------------------------------------------------------
extern "C" void kernel_launch(void* const* d_in, const int* in_sizes, int n_in,
                              void* d_out, int out_size)
{
    const float* x  = (const float*)d_in[0];
    const float* l  = (const float*)d_in[1];
    const float* W1 = (const float*)d_in[2];
    const float* b1 = (const float*)d_in[3];
    const float* W2 = (const float*)d_in[4];
    const float* b2 = (const float*)d_in[5];
    float* out = (float*)d_out;

    static bool attr_set = false;
    if (!attr_set) {
        cudaFuncSetAttribute(gemm_mma_kernel,
                             cudaFuncAttributeMaxDynamicSharedMemorySize, SMEM_GEMM);
        attr_set = true;
    }

    dim3 eg(G_, B_);
    extract_kernel<<<eg, 192>>>(x, l);
    gemm_mma_kernel<<<NCHUNK, 256, SMEM_GEMM>>>(W1);
    finalize_kernel<<<B_, 512>>>(l, b1, W2, b2, out);
}

// round 7
// speedup vs baseline: 1.4273x; 1.0986x over previous
#include <cuda_runtime.h>
#include <cuda_bf16.h>
#include <cstdint>

// Problem constants
#define B_     64
#define H_     512
#define W_     512
#define C_     3
#define G_     64
#define K_     3
#define D_IN   (K_*G_*G_*C_)   // 36864
#define HG_    128
#define HL_    128

// GEMM split-K config
#define NCHUNK 144
#define DC     256             // K-dims per CTA chunk (NCHUNK*DC == D_IN)

// Scratch (device globals; no runtime allocation allowed)
__device__ float g_phi[(size_t)B_ * D_IN];            // 9.4 MB
__device__ float g_part[(size_t)NCHUNK * B_ * HG_];   // 4.7 MB

__device__ __forceinline__ uint32_t smem_u32(const void* p) {
    uint32_t a;
    asm("{ .reg .u64 t; cvta.to.shared.u64 t, %1; cvt.u32.u64 %0, t; }"
        : "=r"(a) : "l"(p));
    return a;
}

// ---------------------------------------------------------------------------
// Kernel 1: fused multi-scale glimpse extraction + avg pooling (v4: LDG.128)
//
// One CTA per (gy2, b). Stages the 4 source rows of the k=2 window (768
// floats each) with ALIGNED float4 loads: misalignment s=(xs*3)&3 is the
// same for every row (row stride 1536 ≡ 0 mod 4), so data lands at buf[j+s].
// Derives k=2 (4x4 pool), k=1 (2x2 pool, central), k=0 (copy, central).
// ---------------------------------------------------------------------------
#define BUFSTR 776   // floats per staged row (768 + shift slack, float4 mult)

__global__ __launch_bounds__(192) void extract_kernel(
    const float* __restrict__ x, const float* __restrict__ l)
{
    __shared__ float buf[4 * BUFSTR];

    const int gy2 = blockIdx.x;
    const int b   = blockIdx.y;
    const int tid = threadIdx.x;

    // denormalize coords exactly like reference: trunc((0.5*(l+1))*512)
    const float lx = __ldg(&l[b * 2 + 0]);
    const float ly = __ldg(&l[b * 2 + 1]);
    const int cx = (int)((0.5f * (lx + 1.0f)) * 512.0f);
    const int cy = (int)((0.5f * (ly + 1.0f)) * 512.0f);
    const int xs = cx - 128;
    const int ys = cy - 128 + gy2 * 4;

    const int jlo = (xs < 0 ? -xs : 0) * 3;
    const int xe  = xs + 256;
    const int jhi = ((xe > W_ ? W_ : xe) - xs) * 3;
    const int s   = (xs * 3) & 3;            // uniform element shift

    // stage 4 contiguous source rows with aligned float4 loads
    #pragma unroll
    for (int rr = 0; rr < 4; rr++) {
        const int y = ys + rr;
        const bool yok = (y >= 0) && (y < H_);
        const float* rowp = x + (((size_t)b * H_ + y) * W_ + xs) * C_;  // elem j at rowp+j
        float* bufRow = &buf[rr * BUFSTR];
        #pragma unroll
        for (int i = tid; i < 193; i += 192) {
            const int e0 = 4 * i - s;                 // first element of this float4
            float4 v = make_float4(0.f, 0.f, 0.f, 0.f);
            if (yok) {
                if (e0 >= jlo && e0 + 3 < jhi) {
                    v = *reinterpret_cast<const float4*>(rowp + e0);  // aligned
                } else if (e0 + 3 >= jlo && e0 < jhi) {
                    float* vp = &v.x;
                    #pragma unroll
                    for (int t = 0; t < 4; t++) {
                        const int e = e0 + t;
                        if (e >= jlo && e < jhi) vp[t] = __ldg(rowp + e);
                    }
                }
            }
            *reinterpret_cast<float4*>(bufRow + 4 * i) = v;  // element j at bufRow[j+s]
        }
    }
    __syncthreads();

    const int gx = tid / 3;
    const int c  = tid - gx * 3;
    float* phiB = &g_phi[(size_t)b * D_IN];
    const float* bufS = buf + s;

    // ---- k=2: pool 4x4 ----
    {
        float sum = 0.0f;
        #pragma unroll
        for (int dy = 0; dy < 4; dy++)
            #pragma unroll
            for (int dx = 0; dx < 4; dx++)
                sum += bufS[dy * BUFSTR + (gx * 4 + dx) * 3 + c];
        phiB[(2 * G_ + gy2) * (G_ * C_) + tid] = sum * (1.0f / 16.0f);
    }

    // ---- k=1: two output rows, pool 2x2 over central 128 cols ----
    if (gy2 >= 16 && gy2 < 48) {
        #pragma unroll
        for (int h = 0; h < 2; h++) {
            const int gy1 = 2 * gy2 - 32 + h;
            float sum = 0.0f;
            #pragma unroll
            for (int dy = 0; dy < 2; dy++)
                #pragma unroll
                for (int dx = 0; dx < 2; dx++)
                    sum += bufS[(2 * h + dy) * BUFSTR + (64 + gx * 2 + dx) * 3 + c];
            phiB[(G_ + gy1) * (G_ * C_) + tid] = sum * 0.25f;
        }
    }

    // ---- k=0: four output rows, direct copy of central 64 cols ----
    if (gy2 >= 24 && gy2 < 40) {
        #pragma unroll
        for (int rr = 0; rr < 4; rr++) {
            const int gy0 = 4 * gy2 - 96 + rr;
            phiB[gy0 * (G_ * C_) + tid] = bufS[rr * BUFSTR + (96 + gx) * 3 + c];
        }
    }
}

// ---------------------------------------------------------------------------
// Kernel 2: split-K GEMM via mma.sync bf16 (HMMA), bf16x3 compensated split:
// D = Ah*Bh + Ah*Bl + Al*Bh, fp32 accumulate. Grid 144, 512 threads (16 warps,
// warp = 16m x 32n). DC=256 K-dims as 2 slabs of 128; accs persist.
// ---------------------------------------------------------------------------
#define KSTR   136                       // padded K stride in bf16 (272B rows)
#define A_TILE (64 * KSTR * 2)           // 17408 B
#define B_TILE (128 * KSTR * 2)          // 34816 B
#define OFF_AH 0
#define OFF_AL A_TILE
#define OFF_BH (2 * A_TILE)
#define OFF_BL (2 * A_TILE + B_TILE)
#define SMEM_GEMM (2 * A_TILE + 2 * B_TILE)   // 104448 B

__device__ __forceinline__ void ldsm_x4(uint32_t a[4], uint32_t addr) {
    asm volatile("ldmatrix.sync.aligned.m8n8.x4.shared.b16 {%0,%1,%2,%3}, [%4];"
                 : "=r"(a[0]), "=r"(a[1]), "=r"(a[2]), "=r"(a[3]) : "r"(addr));
}
__device__ __forceinline__ void mma_bf16(
    float c[4], const uint32_t a[4], uint32_t b0, uint32_t b1)
{
    asm volatile(
        "mma.sync.aligned.m16n8k16.row.col.f32.bf16.bf16.f32 "
        "{%0,%1,%2,%3}, {%4,%5,%6,%7}, {%8,%9}, {%0,%1,%2,%3};"
        : "+f"(c[0]), "+f"(c[1]), "+f"(c[2]), "+f"(c[3])
        : "r"(a[0]), "r"(a[1]), "r"(a[2]), "r"(a[3]), "r"(b0), "r"(b1));
}

__device__ __forceinline__ uint32_t hi_lo_pack(float v0, float v1, uint32_t& lo_out)
{
    __nv_bfloat16 h0 = __float2bfloat16(v0);
    __nv_bfloat16 h1 = __float2bfloat16(v1);
    __nv_bfloat16 e0 = __float2bfloat16(v0 - __bfloat162float(h0));
    __nv_bfloat16 e1 = __float2bfloat16(v1 - __bfloat162float(h1));
    __nv_bfloat162 hp; hp.x = h0; hp.y = h1;
    __nv_bfloat162 lp; lp.x = e0; lp.y = e1;
    lo_out = *reinterpret_cast<uint32_t*>(&lp);
    return *reinterpret_cast<uint32_t*>(&hp);
}

__global__ __launch_bounds__(512) void gemm_mma_kernel(const float* __restrict__ W1)
{
    extern __shared__ char smem[];
    const uint32_t sb = smem_u32(smem);
    const int tid  = threadIdx.x;
    const int wid  = tid >> 5;
    const int lane = tid & 31;

    // warp tiling: mt = wid>>2 (m16 tiles 0..3), nq = wid&3 (n32 quarters)
    const int mt = wid >> 2;
    const int nq = wid & 3;

    // ldmatrix relative offsets (bytes)
    const uint32_t aRel = (uint32_t)((mt * 16 + (lane & 15)) * (KSTR * 2)
                                     + (lane >> 4) * 16);
    // B x4: lanes 0-7 -> (n+0,k0..7), 8-15 -> (n+0,k8..15), 16-23 -> (n+8,k0..7), 24-31 -> (n+8,k8..15)
    const uint32_t bRel = (uint32_t)((nq * 32 + ((lane >> 4) * 8) + (lane & 7)) * (KSTR * 2)
                                     + (((lane >> 3) & 1) * 16));

    float acc[4][4];
    #pragma unroll
    for (int nt = 0; nt < 4; nt++)
        #pragma unroll
        for (int j = 0; j < 4; j++) acc[nt][j] = 0.0f;

    for (int slab = 0; slab < 2; slab++) {
        const int d0 = blockIdx.x * DC + slab * 128;

        if (slab) __syncthreads();   // protect smem reuse

        // ---- fill A (phi 64 x 128) hi/lo ----
        for (int idx = tid; idx < 64 * 64; idx += 512) {
            const int m  = idx >> 6;
            const int kp = idx & 63;
            const float2 p = *reinterpret_cast<const float2*>(
                &g_phi[(size_t)m * D_IN + d0 + 2 * kp]);
            uint32_t lo, hi = hi_lo_pack(p.x, p.y, lo);
            const int off = m * (KSTR * 2) + kp * 4;
            *reinterpret_cast<uint32_t*>(smem + OFF_AH + off) = hi;
            *reinterpret_cast<uint32_t*>(smem + OFF_AL + off) = lo;
        }

        // ---- fill B^T (128 n x 128 k): B[n][k] = W1[d0+k][n] ----
        for (int idx = tid; idx < 64 * 128; idx += 512) {
            const int kk = idx >> 7;
            const int n  = idx & 127;
            const float v0 = __ldg(&W1[(size_t)(d0 + 2 * kk)     * HG_ + n]);
            const float v1 = __ldg(&W1[(size_t)(d0 + 2 * kk + 1) * HG_ + n]);
            uint32_t lo, hi = hi_lo_pack(v0, v1, lo);
            const int off = n * (KSTR * 2) + kk * 4;
            *reinterpret_cast<uint32_t*>(smem + OFF_BH + off) = hi;
            *reinterpret_cast<uint32_t*>(smem + OFF_BL + off) = lo;
        }
        __syncthreads();

        // ---- 3 compensated passes over this slab ----
        #pragma unroll
        for (int pass = 0; pass < 3; pass++) {
            const uint32_t aBase = sb + ((pass == 2) ? OFF_AL : OFF_AH) + aRel;
            const uint32_t bBase = sb + ((pass == 1) ? OFF_BL : OFF_BH) + bRel;
            #pragma unroll
            for (int kt = 0; kt < 8; kt++) {
                uint32_t a[4];
                ldsm_x4(a, aBase + kt * 32);
                #pragma unroll
                for (int np = 0; np < 2; np++) {      // pairs of n-tiles
                    uint32_t bq[4];
                    ldsm_x4(bq, bBase + np * 16 * (KSTR * 2) + kt * 32);
                    mma_bf16(acc[np * 2 + 0], a, bq[0], bq[1]);
                    mma_bf16(acc[np * 2 + 1], a, bq[2], bq[3]);
                }
            }
        }
    }

    // ---- epilogue: write 64x128 partial tile ----
    float* part = &g_part[(size_t)blockIdx.x * (B_ * HG_)];
    const int qid = lane >> 2;
    const int tq  = lane & 3;
    const int row0 = mt * 16 + qid;
    #pragma unroll
    for (int nt = 0; nt < 4; nt++) {
        const int col = nq * 32 + nt * 8 + tq * 2;
        float2 v0; v0.x = acc[nt][0]; v0.y = acc[nt][1];
        float2 v1; v1.x = acc[nt][2]; v1.y = acc[nt][3];
        *reinterpret_cast<float2*>(part + row0 * HG_ + col) = v0;
        *reinterpret_cast<float2*>(part + (row0 + 8) * HG_ + col) = v1;
    }
}

// ---------------------------------------------------------------------------
// Kernel 3: reduce partials + bias + relu + l-branch.
// ---------------------------------------------------------------------------
__global__ __launch_bounds__(512) void finalize_kernel(
    const float* __restrict__ l, const float* __restrict__ b1,
    const float* __restrict__ W2, const float* __restrict__ b2,
    float* __restrict__ out)
{
    __shared__ float red[4][HG_];
    const int b = blockIdx.x;
    const int tid = threadIdx.x;
    const int h = tid & 127;
    const int p = tid >> 7;

    float s = 0.0f;
    #pragma unroll 9
    for (int c = p; c < NCHUNK; c += 4)
        s += g_part[(size_t)c * (B_ * HG_) + b * HG_ + h];
    red[p][h] = s;
    __syncthreads();

    if (p == 0) {
        const float v = red[0][h] + red[1][h] + red[2][h] + red[3][h] + b1[h];
        out[b * (HG_ + HL_) + h] = fmaxf(v, 0.0f);
        const float lw = l[b * 2 + 0] * W2[h] + l[b * 2 + 1] * W2[HL_ + h] + b2[h];
        out[b * (HG_ + HL_) + HG_ + h] = fmaxf(lw, 0.0f);
    }
}

// ---------------------------------------------------------------------------
extern "C" void kernel_launch(void* const* d_in, const int* in_sizes, int n_in,
                              void* d_out, int out_size)
{
    const float* x  = (const float*)d_in[0];
    const float* l  = (const float*)d_in[1];
    const float* W1 = (const float*)d_in[2];
    const float* b1 = (const float*)d_in[3];
    const float* W2 = (const float*)d_in[4];
    const float* b2 = (const float*)d_in[5];
    float* out = (float*)d_out;

    static bool attr_set = false;
    if (!attr_set) {
        cudaFuncSetAttribute(gemm_mma_kernel,
                             cudaFuncAttributeMaxDynamicSharedMemorySize, SMEM_GEMM);
        attr_set = true;
    }

    dim3 eg(G_, B_);
    extract_kernel<<<eg, 192>>>(x, l);
    gemm_mma_kernel<<<NCHUNK, 512, SMEM_GEMM>>>(W1);
    finalize_kernel<<<B_, 512>>>(l, b1, W2, b2, out);
}